// round 16
// baseline (speedup 1.0000x reference)
#include <cuda_runtime.h>
#include <math.h>

// RoI Align pyramid (FPN) — persistent static-interleaved warp pipeline.
//   d_in[0] metadata [1,3] f32, d_in[1] boxes [1,1024,4] f32
//   d_in[2..5] p2..p5: [1,H,H,256] f32, H = 256,128,64,32
// Output: [1,1024,7,7,256] f32
//
// Work item = one grid row (box, gy) = 7 samples -> 7168 uniform items.
// Grid = 592 CTAs x 64 thr (2 warps) = 1184 persistent warps; warp g
// statically owns items g, g+1184, ... (6-7 items from ~6 different
// boxes -> difficulty variance averages out; tail = 1 item). Each warp
// runs a 3-deep 4KB-stage cp.async.bulk ring that rolls CONTINUOUSLY
// across item/box boundaries (one pipeline prologue per warp total,
// vs one per box before). Per-(warp,slot) mbarrier completion,
// parity = consume-count/DEPTH & 1. No block barriers. __stcs stores.

#define EXTENT 7
#define NSAMP  49
#define NBOX   1024
#define CH4    64u   // 256 channels / 4
#define DEPTH  3
#define GRID   592
#define NWARP  (GRID * 2)          // 1184
#define NITEMS (NBOX * EXTENT)     // 7168

__device__ __forceinline__ unsigned smem_u32(const void* p) {
    return (unsigned)__cvta_generic_to_shared(p);
}
__device__ __forceinline__ void mbar_init(unsigned mb, unsigned count) {
    asm volatile("mbarrier.init.shared.b64 [%0], %1;" :: "r"(mb), "r"(count) : "memory");
}
__device__ __forceinline__ void mbar_expect_tx(unsigned mb, unsigned bytes) {
    asm volatile("mbarrier.arrive.expect_tx.shared.b64 _, [%0], %1;"
                 :: "r"(mb), "r"(bytes) : "memory");
}
__device__ __forceinline__ void mbar_wait_parity(unsigned mb, unsigned parity) {
    asm volatile(
        "{\n\t"
        ".reg .pred P;\n\t"
        "WAIT_%=:\n\t"
        "mbarrier.try_wait.parity.acquire.cta.shared::cta.b64 P, [%0], %1, 0x989680;\n\t"
        "@P bra.uni DONE_%=;\n\t"
        "bra.uni WAIT_%=;\n\t"
        "DONE_%=:\n\t"
        "}"
        :: "r"(mb), "r"(parity) : "memory");
}
__device__ __forceinline__ void bulk_g2s(unsigned sdst, const void* gsrc,
                                         unsigned bytes, unsigned mb) {
    asm volatile(
        "cp.async.bulk.shared::cta.global.mbarrier::complete_tx::bytes [%0], [%1], %2, [%3];"
        :: "r"(sdst), "l"(gsrc), "r"(bytes), "r"(mb) : "memory");
}

__global__ __launch_bounds__(64, 4)
void roi_align_pyramid_kernel(const float* __restrict__ metadata,
                              const float* __restrict__ boxes,
                              const float* __restrict__ p2,
                              const float* __restrict__ p3,
                              const float* __restrict__ p4,
                              const float* __restrict__ p5,
                              float* __restrict__ out)
{
    // [warp][stage][corner][chunk] = 2*3*4*64*16B = 24KB
    __shared__ __align__(128) float4 buf[2][DEPTH][4][CH4];
    __shared__ unsigned long long mbar[2][DEPTH];

    const unsigned t  = threadIdx.x;
    const unsigned wp = t >> 5;
    const unsigned l  = t & 31u;

    if (l == 0) {
        #pragma unroll
        for (int st = 0; st < DEPTH; st++)
            mbar_init(smem_u32(&mbar[wp][st]), 1);
    }
    __syncwarp();

    const float rows = metadata[0];
    const float cols = metadata[1];
    const float inv_r = 1.0f / (rows - 1.0f);
    const float inv_c = 1.0f / (cols - 1.0f);
    const float inv_log2 = 1.0f / logf(2.0f);
    const float inv_area_sqrt = 1.0f / sqrtf(rows * cols);

    const unsigned g = blockIdx.x * 2u + wp;   // global warp id 0..1183

    float4* __restrict__ o4 = (float4*)out;

    // Per-(item e, gx) setup. Returns everything; call sites use subsets.
    struct SInfo {
        const float4* f4;
        unsigned base, rowstep, obase;
        float w00, w01, w10, w11;
    };
    auto setup = [&](int e, int gx) -> SInfo {
        SInfo si;
        const int box = e / EXTENT;
        const int gy  = e - box * EXTENT;

        const float x1 = __ldg(&boxes[box * 4 + 0]);
        const float y1 = __ldg(&boxes[box * 4 + 1]);
        const float x2 = __ldg(&boxes[box * 4 + 2]);
        const float y2 = __ldg(&boxes[box * 4 + 3]);
        const float h = y2 - y1;
        const float w = x2 - x1;

        float rl = logf(sqrtf(h * w) * inv_area_sqrt) * inv_log2;
        rl = fminf(5.0f, fmaxf(2.0f, 4.0f + rintf(rl)));
        const int lvl = (int)rl;
        const float* feat;
        int H;
        switch (lvl) {
            case 2: feat = p2; H = 256; break;
            case 3: feat = p3; H = 128; break;
            case 4: feat = p4; H = 64;  break;
            default: feat = p5; H = 32; break;
        }
        const int W = H;

        const float ny1 = y1 * inv_r;
        const float nx1 = x1 * inv_c;
        const float dny = (y2 - y1) * inv_r;
        const float dnx = (x2 - x1) * inv_c;
        const float gyf = (float)gy * (1.0f / (float)(EXTENT - 1));
        const float gxf = (float)gx * (1.0f / (float)(EXTENT - 1));
        const float ys = (ny1 + dny * gyf) * (float)(H - 1);
        const float xs = (nx1 + dnx * gxf) * (float)(W - 1);

        const float y0f = fminf(fmaxf(floorf(ys), 0.0f), (float)(H - 2));
        const float x0f = fminf(fmaxf(floorf(xs), 0.0f), (float)(W - 2));
        const float wy = ys - y0f;
        const float wx = xs - x0f;
        si.w00 = (1.0f - wy) * (1.0f - wx);
        si.w01 = (1.0f - wy) * wx;
        si.w10 = wy * (1.0f - wx);
        si.w11 = wy * wx;

        si.f4      = (const float4*)feat;
        si.base    = ((unsigned)((int)y0f * W + (int)x0f)) * CH4;
        si.rowstep = (unsigned)W * CH4;
        si.obase   = (unsigned)box * (NSAMP * CH4) + (unsigned)(gy * EXTENT + gx) * CH4;
        return si;
    };

    // issue stage: lane 0 bulk-copies 4x1KB for (e,gx) into slot st
    auto issue = [&](int e, int gx, int st) {
        if (l == 0) {
            SInfo si = setup(e, gx);
            const unsigned mb = smem_u32(&mbar[wp][st]);
            mbar_expect_tx(mb, 4096);
            bulk_g2s(smem_u32(&buf[wp][st][0][0]), &si.f4[si.base],                    1024, mb);
            bulk_g2s(smem_u32(&buf[wp][st][1][0]), &si.f4[si.base + CH4],              1024, mb);
            bulk_g2s(smem_u32(&buf[wp][st][2][0]), &si.f4[si.base + si.rowstep],       1024, mb);
            bulk_g2s(smem_u32(&buf[wp][st][3][0]), &si.f4[si.base + si.rowstep + CH4], 1024, mb);
        }
    };

    // item count for this warp: items e = g, g+NWARP, ...
    const int nit   = (NITEMS - (int)g + NWARP - 1) / NWARP;   // 6 or 7
    const int total = nit * EXTENT;                             // samples (>= 42)

    // cursors
    int e_i = (int)g, gx_i = 0;   // issue
    int e_c = (int)g, gx_c = 0;   // compute
    auto advance = [&](int& e, int& gx) {
        if (++gx == EXTENT) { gx = 0; e += NWARP; }
    };

    // prologue (every warp has >= 42 samples, so 3 issues always valid)
    issue(e_i, gx_i, 0); advance(e_i, gx_i);
    issue(e_i, gx_i, 1); advance(e_i, gx_i);
    issue(e_i, gx_i, 2); advance(e_i, gx_i);

    int st = 0, ph = 0;
    for (int j = 0; j < total; j++) {
        SInfo si = setup(e_c, gx_c);

        mbar_wait_parity(smem_u32(&mbar[wp][st]), (unsigned)ph);

        const float4 a00 = buf[wp][st][0][l];
        const float4 a01 = buf[wp][st][1][l];
        const float4 a10 = buf[wp][st][2][l];
        const float4 a11 = buf[wp][st][3][l];
        float4 ra;
        ra.x = a00.x * si.w00 + a01.x * si.w01 + a10.x * si.w10 + a11.x * si.w11;
        ra.y = a00.y * si.w00 + a01.y * si.w01 + a10.y * si.w10 + a11.y * si.w11;
        ra.z = a00.z * si.w00 + a01.z * si.w01 + a10.z * si.w10 + a11.z * si.w11;
        ra.w = a00.w * si.w00 + a01.w * si.w01 + a10.w * si.w10 + a11.w * si.w11;
        __stcs(&o4[si.obase + l], ra);

        const float4 b00 = buf[wp][st][0][l + 32];
        const float4 b01 = buf[wp][st][1][l + 32];
        const float4 b10 = buf[wp][st][2][l + 32];
        const float4 b11 = buf[wp][st][3][l + 32];
        float4 rb;
        rb.x = b00.x * si.w00 + b01.x * si.w01 + b10.x * si.w10 + b11.x * si.w11;
        rb.y = b00.y * si.w00 + b01.y * si.w01 + b10.y * si.w10 + b11.y * si.w11;
        rb.z = b00.z * si.w00 + b01.z * si.w01 + b10.z * si.w10 + b11.z * si.w11;
        rb.w = b00.w * si.w00 + b01.w * si.w01 + b10.w * si.w10 + b11.w * si.w11;
        __stcs(&o4[si.obase + l + 32], rb);

        // refill the slot just drained with the next scheduled sample
        if (e_i < NITEMS) {
            issue(e_i, gx_i, st);
            advance(e_i, gx_i);
        }
        advance(e_c, gx_c);
        if (++st == DEPTH) { st = 0; ph ^= 1; }
    }
}

extern "C" void kernel_launch(void* const* d_in, const int* in_sizes, int n_in,
                              void* d_out, int out_size)
{
    const float* metadata = (const float*)d_in[0];
    const float* boxes    = (const float*)d_in[1];
    const float* p2       = (const float*)d_in[2];
    const float* p3       = (const float*)d_in[3];
    const float* p4       = (const float*)d_in[4];
    const float* p5       = (const float*)d_in[5];
    float* out = (float*)d_out;

    roi_align_pyramid_kernel<<<GRID, 64>>>(metadata, boxes, p2, p3, p4, p5, out);
}